// round 14
// baseline (speedup 1.0000x reference)
#include <cuda_runtime.h>
#include <cuda_bf16.h>
#include <math.h>
#include <stdint.h>

#define TT 5
#define NNODE 20000
#define EDGES 320000
#define DIM 256
#define NH 8
#define HD 32
#define BNB 4096
#define BCB 2048
#define GD 1024 /* 4*DIM */

// ------------------------------------------------------------------
// Static device scratch (no allocations allowed anywhere).
// ------------------------------------------------------------------
struct Scratch {
  alignas(16) float dsrc[TT * NNODE * NH];
  alignas(16) float ddst[TT * NNODE * NH];
  alignas(16) float csum5[TT * DIM];
  alignas(16) float csq5[TT * DIM];
  alignas(16) float scl5[TT * DIM];
  alignas(16) float sft5[TT * DIM];
  alignas(16) float hbuf[TT * NNODE * DIM];
  alignas(16) float aggA[TT * NNODE * DIM];
  alignas(16) float aggB[TT * NNODE * DIM];
  alignas(16) float clfH[NNODE * DIM];
  alignas(16) float dsrcC[NNODE * NH];
  alignas(16) float ddstC[NNODE * NH];
  alignas(16) int   deg5[TT * NNODE];
  alignas(16) int   fill5[TT * NNODE];
  alignas(16) int   rowptr5[TT * (NNODE + 1)];
  alignas(16) int   esrc5[TT * EDGES];
  alignas(16) int   eid5[TT * EDGES];
  alignas(16) float atts[EDGES];
  alignas(16) int   argm[NNODE];
  alignas(16) float xx[2 * BNB * TT * DIM];   // [0]=x fwd, [1]=xrev
  alignas(16) int   flag[BNB * TT];
  alignas(16) int   lens[BNB];
  alignas(16) int   maxlen;
  alignas(16) float Gpre[2 * BNB * TT * GD];  // fwd half, bwd half
  alignas(16) float h[2 * BNB * DIM];         // keep h,c adjacent (joint zero)
  alignas(16) float c[2 * BNB * DIM];
  alignas(16) float hs[2 * BNB * TT * DIM];   // hsf then hsb
  alignas(16) float pooled[BNB * DIM];
  alignas(16) float bias2[2 * GD];
  alignas(16) float hclf[BCB * DIM];
  // fragment-ready bf16 splits of B operands (u32 = 2 packed bf16)
  alignas(16) uint32_t gWh[2 * DIM * 128];
  alignas(16) uint32_t gWl[2 * DIM * 128];
  alignas(16) uint32_t cWh[DIM * 128];
  alignas(16) uint32_t cWl[DIM * 128];
  alignas(16) uint32_t wihh[2 * GD * 128];
  alignas(16) uint32_t wihl[2 * GD * 128];
  alignas(16) uint32_t whhh[2 * GD * 128];
  alignas(16) uint32_t whhl[2 * GD * 128];
};
__device__ Scratch S;

__device__ __forceinline__ float sigmf(float x) { return 1.f / (1.f + expf(-x)); }

// ------------------------------------------------------------------
// mma helpers
// ------------------------------------------------------------------
__device__ __forceinline__ void ldsm4(uint32_t& r0, uint32_t& r1, uint32_t& r2, uint32_t& r3,
                                      const void* p) {
  uint32_t a = (uint32_t)__cvta_generic_to_shared(p);
  asm volatile("ldmatrix.sync.aligned.m8n8.x4.shared.b16 {%0,%1,%2,%3}, [%4];"
               : "=r"(r0), "=r"(r1), "=r"(r2), "=r"(r3) : "r"(a));
}
__device__ __forceinline__ void mma16816(float* d, const uint32_t* a, const uint32_t* b) {
  asm volatile(
      "mma.sync.aligned.m16n8k16.row.col.f32.bf16.bf16.f32 "
      "{%0,%1,%2,%3}, {%4,%5,%6,%7}, {%8,%9}, {%0,%1,%2,%3};"
      : "+f"(d[0]), "+f"(d[1]), "+f"(d[2]), "+f"(d[3])
      : "r"(a[0]), "r"(a[1]), "r"(a[2]), "r"(a[3]), "r"(b[0]), "r"(b[1]));
}
__device__ __forceinline__ void split2(float x, unsigned short& h, unsigned short& l) {
  __nv_bfloat16 hb = __float2bfloat16(x);
  h = __bfloat16_as_ushort(hb);
  l = __bfloat16_as_ushort(__float2bfloat16(x - __bfloat162float(hb)));
}

// ------------------------------------------------------------------
// utilities
// ------------------------------------------------------------------
__global__ void k_zerof(float* p, int n) {
  for (int i = blockIdx.x * blockDim.x + threadIdx.x; i < n; i += gridDim.x * blockDim.x) p[i] = 0.f;
}
__global__ void k_zeroi(int* p, int n) {
  for (int i = blockIdx.x * blockDim.x + threadIdx.x; i < n; i += gridDim.x * blockDim.x) p[i] = 0;
}

// ------------------------------------------------------------------
// fragment-ready weight splits (K = 256 fixed).
// layout: u32 idx = ((n8*16 + k16)*2 + r)*32 + lane
// content: pack(B[n8*8 + lane/4][k16*16 + r*8 + 2*(lane&3)], same+1)
// ------------------------------------------------------------------
__global__ void k_splitFT(const float* __restrict__ W /*[K=256][N]*/, uint32_t* oh, uint32_t* ol,
                          int N) {
  int i = blockIdx.x * 256 + threadIdx.x;  // over N*128
  if (i >= N * 128) return;
  int l = i & 31, r = (i >> 5) & 1, k16 = (i >> 6) & 15, n8 = i >> 10;
  int n = n8 * 8 + (l >> 2);
  int k = k16 * 16 + r * 8 + 2 * (l & 3);
  float s0 = W[(size_t)k * N + n];
  float s1 = W[(size_t)(k + 1) * N + n];
  unsigned short h0, l0, h1, l1;
  split2(s0, h0, l0);
  split2(s1, h1, l1);
  oh[i] = (uint32_t)h0 | ((uint32_t)h1 << 16);
  ol[i] = (uint32_t)l0 | ((uint32_t)l1 << 16);
}
__global__ void k_splitFD(const float* __restrict__ W /*[N][K=256]*/, uint32_t* oh, uint32_t* ol,
                          int N) {
  int i = blockIdx.x * 256 + threadIdx.x;
  if (i >= N * 128) return;
  int l = i & 31, r = (i >> 5) & 1, k16 = (i >> 6) & 15, n8 = i >> 10;
  int n = n8 * 8 + (l >> 2);
  int k = k16 * 16 + r * 8 + 2 * (l & 3);
  float s0 = W[(size_t)n * 256 + k];
  float s1 = W[(size_t)n * 256 + k + 1];
  unsigned short h0, l0, h1, l1;
  split2(s0, h0, l0);
  split2(s1, h1, l1);
  oh[i] = (uint32_t)h0 | ((uint32_t)h1 << 16);
  ol[i] = (uint32_t)l0 | ((uint32_t)l1 << 16);
}

__global__ void k_addb(const float* a, const float* b, float* o, int n) {
  int i = blockIdx.x * 256 + threadIdx.x;
  if (i < n) o[i] = a[i] + b[i];
}

// ------------------------------------------------------------------
// BN stats (chunked) + finalize (head only)
// ------------------------------------------------------------------
__global__ void k_bnstats5(const float* __restrict__ x, int M, float* csum, float* csq) {
  __shared__ float sh[2][8][32];
  int g = blockIdx.y;
  int lane = threadIdx.x & 31, rth = threadIdx.x >> 5;
  int col = blockIdx.x * 32 + lane;
  int nch = gridDim.z, ch = blockIdx.z;
  int r0 = (int)(((long long)M * ch) / nch), r1 = (int)(((long long)M * (ch + 1)) / nch);
  const float* xg = x + (size_t)g * M * DIM;
  float s = 0.f, q = 0.f;
  for (int r = r0 + rth; r < r1; r += 8) {
    float v = xg[(size_t)r * DIM + col];
    s += v;
    q += v * v;
  }
  sh[0][rth][lane] = s;
  sh[1][rth][lane] = q;
  __syncthreads();
  if (rth == 0) {
#pragma unroll
    for (int i = 1; i < 8; i++) {
      s += sh[0][i][lane];
      q += sh[1][i][lane];
    }
    atomicAdd(&csum[g * DIM + col], s);
    atomicAdd(&csq[g * DIM + col], q);
  }
}

__global__ void k_bnfin5(const float* csum, const float* csq, const float* __restrict__ g,
                         const float* __restrict__ b, float Minv, float* scl, float* sft) {
  int gg = blockIdx.x, d = threadIdx.x;
  float mu = csum[gg * DIM + d] * Minv;
  float var = csq[gg * DIM + d] * Minv - mu * mu;
  float rs = rsqrtf(var + 1e-5f);
  float sc = g[d] * rs;
  scl[gg * DIM + d] = sc;
  sft[gg * DIM + d] = b[d] - mu * sc;
}

// ------------------------------------------------------------------
// HMMA split-bf16 GEMM. A double-buffered in smem; B fragments loaded
// directly from global (fragment-ready layout) with REGISTER DOUBLE-BUFFER
// prefetch one np-group ahead (covers the L2 latency).
// MODE 0: +bias. MODE 1: BN on A + bias + fused per-head dots. MODE 2: accum.
// Rows >= Msplit use (Bh2,Bl2,biasB).
// ------------------------------------------------------------------
#define SPITCH 24
#define STILE (128 * SPITCH * 2) /* bytes per bf16 tile: 6144 */

template <int MODE>
__device__ __forceinline__ void stage_store(char* dyn, int s, int sr, int sc, float4 f0,
                                            float4 f1, const float* __restrict__ csum,
                                            const float* __restrict__ csq,
                                            const float* __restrict__ gma,
                                            const float* __restrict__ bta, float Minv, int gbase,
                                            int cbase) {
  float v[8] = {f0.x, f0.y, f0.z, f0.w, f1.x, f1.y, f1.z, f1.w};
  if (MODE == 1) {
#pragma unroll
    for (int j = 0; j < 8; j++) {
      int cc = cbase + j;
      float mu = csum[gbase + cc] * Minv;
      float var = csq[gbase + cc] * Minv - mu * mu;
      float scv = gma[cc] * rsqrtf(var + 1e-5f);
      v[j] = v[j] * scv + (bta[cc] - mu * scv);
    }
  }
  unsigned short hsv[8], lsv[8];
#pragma unroll
  for (int j = 0; j < 8; j++) split2(v[j], hsv[j], lsv[j]);
  uint4 pa, pl;
  pa.x = (uint32_t)hsv[0] | ((uint32_t)hsv[1] << 16);
  pa.y = (uint32_t)hsv[2] | ((uint32_t)hsv[3] << 16);
  pa.z = (uint32_t)hsv[4] | ((uint32_t)hsv[5] << 16);
  pa.w = (uint32_t)hsv[6] | ((uint32_t)hsv[7] << 16);
  pl.x = (uint32_t)lsv[0] | ((uint32_t)lsv[1] << 16);
  pl.y = (uint32_t)lsv[2] | ((uint32_t)lsv[3] << 16);
  pl.z = (uint32_t)lsv[4] | ((uint32_t)lsv[5] << 16);
  pl.w = (uint32_t)lsv[6] | ((uint32_t)lsv[7] << 16);
  size_t off = (size_t)s * STILE + sr * (SPITCH * 2) + sc * 2;
  *(uint4*)(dyn + off) = pa;
  *(uint4*)(dyn + 2 * STILE + off) = pl;
}

template <int MODE>
__global__ __launch_bounds__(256, 2) void k_mgemm(
    const float* __restrict__ A, int lda, const uint32_t* __restrict__ Bh_g,
    const uint32_t* __restrict__ Bl_g, const uint32_t* __restrict__ Bh2_g,
    const uint32_t* __restrict__ Bl2_g, float* __restrict__ C, int ldc,
    const float* __restrict__ bias, const float* __restrict__ biasB, int Msplit,
    const float* __restrict__ csum, const float* __restrict__ csq,
    const float* __restrict__ gma, const float* __restrict__ bta, float Minv, int nper,
    const float* __restrict__ asrc, const float* __restrict__ adst, float* __restrict__ dsrc,
    float* __restrict__ ddst, int M) {
  __shared__ __align__(16) char dyn[4 * STILE];  // 24KB: Ah,Al x 2 stages
  const int tid = threadIdx.x, lane = tid & 31, wid = tid >> 5;
  const int wm = wid & 3, wn = wid >> 2;
  const int row0 = blockIdx.y * 128, col0 = blockIdx.x * 128;
  const bool second = (row0 >= Msplit);
  const uint32_t* BhU = second ? Bh2_g : Bh_g;
  const uint32_t* BlU = second ? Bl2_g : Bl_g;
  const float* biasU = second ? biasB : bias;

  float acc[2][8][4];
#pragma unroll
  for (int i = 0; i < 2; i++)
#pragma unroll
    for (int j = 0; j < 8; j++)
#pragma unroll
      for (int q = 0; q < 4; q++) acc[i][j][q] = 0.f;

  int arow = row0 + (tid >> 1);
  if (arow >= M) arow = M - 1;
  const int sc = (tid & 1) * 8;
  const float* Ap = A + (size_t)arow * lda + sc;
  int gbase = (MODE == 1) ? (arow / nper) * DIM : 0;
  const int sr = tid >> 1;
  const int n8w = (col0 + wn * 64) >> 3;

  {
    float4 f0 = *(const float4*)(Ap);
    float4 f1 = *(const float4*)(Ap + 4);
    stage_store<MODE>(dyn, 0, sr, sc, f0, f1, csum, csq, gma, bta, Minv, gbase, sc);
  }
  float4 pf0 = *(const float4*)(Ap + 16);
  float4 pf1 = *(const float4*)(Ap + 20);

  // B prefetch: (k16=0, np=0)
  uint32_t bhc[4], blc[4], bhn[4], bln[4];
  {
    int idx0 = (n8w * 16 + 0) * 64 + lane;
    bhc[0] = BhU[idx0];
    bhc[1] = BhU[idx0 + 32];
    bhc[2] = BhU[idx0 + 1024];
    bhc[3] = BhU[idx0 + 1056];
    blc[0] = BlU[idx0];
    blc[1] = BlU[idx0 + 32];
    blc[2] = BlU[idx0 + 1024];
    blc[3] = BlU[idx0 + 1056];
  }
  __syncthreads();

  for (int kc = 0; kc < 256; kc += 16) {
    const int s = (kc >> 4) & 1;
    const int k16 = kc >> 4;
    char* base = dyn + (size_t)s * STILE;
    uint32_t ah[2][4], al[2][4];
#pragma unroll
    for (int mt = 0; mt < 2; mt++) {
      int r = wm * 32 + mt * 16 + (lane & 15);
      int half = (lane >> 4) * 8;
      ldsm4(ah[mt][0], ah[mt][1], ah[mt][2], ah[mt][3], base + r * (SPITCH * 2) + half * 2);
      ldsm4(al[mt][0], al[mt][1], al[mt][2], al[mt][3],
            base + 2 * STILE + r * (SPITCH * 2) + half * 2);
    }
    if (kc + 16 < 256) {
      stage_store<MODE>(dyn, s ^ 1, sr, sc, pf0, pf1, csum, csq, gma, bta, Minv, gbase,
                        kc + 16 + sc);
      if (kc + 32 < 256) {
        pf0 = *(const float4*)(Ap + kc + 32);
        pf1 = *(const float4*)(Ap + kc + 36);
      }
    }
#pragma unroll
    for (int np = 0; np < 4; np++) {
      // prefetch next B fragment group (np+1, or (k16+1, 0) across the boundary)
      if (np < 3 || k16 < 15) {
        int nk16 = (np < 3) ? k16 : k16 + 1;
        int nnp = (np < 3) ? np + 1 : 0;
        int n8 = n8w + nnp * 2;
        int idx0 = (n8 * 16 + nk16) * 64 + lane;
        bhn[0] = BhU[idx0];
        bhn[1] = BhU[idx0 + 32];
        bhn[2] = BhU[idx0 + 1024];
        bhn[3] = BhU[idx0 + 1056];
        bln[0] = BlU[idx0];
        bln[1] = BlU[idx0 + 32];
        bln[2] = BlU[idx0 + 1024];
        bln[3] = BlU[idx0 + 1056];
      }
      mma16816(acc[0][2 * np], ah[0], bhc);
      mma16816(acc[1][2 * np], ah[1], bhc);
      mma16816(acc[0][2 * np + 1], ah[0], bhc + 2);
      mma16816(acc[1][2 * np + 1], ah[1], bhc + 2);
      mma16816(acc[0][2 * np], ah[0], blc);
      mma16816(acc[1][2 * np], ah[1], blc);
      mma16816(acc[0][2 * np + 1], ah[0], blc + 2);
      mma16816(acc[1][2 * np + 1], ah[1], blc + 2);
      mma16816(acc[0][2 * np], al[0], bhc);
      mma16816(acc[1][2 * np], al[1], bhc);
      mma16816(acc[0][2 * np + 1], al[0], bhc + 2);
      mma16816(acc[1][2 * np + 1], al[1], bhc + 2);
#pragma unroll
      for (int j = 0; j < 4; j++) {
        bhc[j] = bhn[j];
        blc[j] = bln[j];
      }
    }
    __syncthreads();
  }

  // ---- epilogue ----
  const int qlane = lane & 3;
  const int hA = (col0 + wn * 64) >> 5;
#pragma unroll
  for (int mt = 0; mt < 2; mt++) {
    int r = row0 + wm * 32 + mt * 16 + (lane >> 2);
    float dA0[2] = {0.f, 0.f}, dA1[2] = {0.f, 0.f};
    float dB0[2] = {0.f, 0.f}, dB1[2] = {0.f, 0.f};
#pragma unroll
    for (int nt = 0; nt < 8; nt++) {
      int cloc = wn * 64 + nt * 8 + qlane * 2;
      float b0 = 0.f, b1 = 0.f;
      if (MODE != 2 && biasU) {
        b0 = biasU[col0 + cloc];
        b1 = biasU[col0 + cloc + 1];
      }
      float c0 = acc[mt][nt][0] + b0, c1 = acc[mt][nt][1] + b1;
      float c2 = acc[mt][nt][2] + b0, c3 = acc[mt][nt][3] + b1;
      size_t off0 = (size_t)r * ldc + col0 + cloc;
      size_t off8 = off0 + (size_t)8 * ldc;
      if (MODE == 2) {
        if (r < M) {
          float2 o = *(const float2*)(C + off0);
          c0 += o.x;
          c1 += o.y;
        }
        if (r + 8 < M) {
          float2 o = *(const float2*)(C + off8);
          c2 += o.x;
          c3 += o.y;
        }
      }
      if (r < M) *(float2*)(C + off0) = make_float2(c0, c1);
      if (r + 8 < M) *(float2*)(C + off8) = make_float2(c2, c3);
      if (MODE == 1) {
        int hh = nt >> 2;
        float as0 = asrc[col0 + cloc], as1 = asrc[col0 + cloc + 1];
        float ad0 = adst[col0 + cloc], ad1 = adst[col0 + cloc + 1];
        dA0[hh] += c0 * as0 + c1 * as1;
        dA1[hh] += c2 * as0 + c3 * as1;
        dB0[hh] += c0 * ad0 + c1 * ad1;
        dB1[hh] += c2 * ad0 + c3 * ad1;
      }
    }
    if (MODE == 1) {
#pragma unroll
      for (int off = 1; off <= 2; off <<= 1) {
#pragma unroll
        for (int hh = 0; hh < 2; hh++) {
          dA0[hh] += __shfl_xor_sync(0xffffffffu, dA0[hh], off);
          dA1[hh] += __shfl_xor_sync(0xffffffffu, dA1[hh], off);
          dB0[hh] += __shfl_xor_sync(0xffffffffu, dB0[hh], off);
          dB1[hh] += __shfl_xor_sync(0xffffffffu, dB1[hh], off);
        }
      }
      if (qlane == 0) {
        if (r < M) {
          dsrc[(size_t)r * NH + hA] = dA0[0];
          dsrc[(size_t)r * NH + hA + 1] = dA0[1];
          ddst[(size_t)r * NH + hA] = dB0[0];
          ddst[(size_t)r * NH + hA + 1] = dB0[1];
        }
        if (r + 8 < M) {
          dsrc[(size_t)(r + 8) * NH + hA] = dA1[0];
          dsrc[(size_t)(r + 8) * NH + hA + 1] = dA1[1];
          ddst[(size_t)(r + 8) * NH + hA] = dB1[0];
          ddst[(size_t)(r + 8) * NH + hA + 1] = dB1[1];
        }
      }
    }
  }
}

// ------------------------------------------------------------------
// CSR build (all 5 graphs)
// ------------------------------------------------------------------
__global__ void k_count5(const int* __restrict__ edges, int* deg5) {
  int i = blockIdx.x * 256 + threadIdx.x;
  if (i >= TT * EDGES) return;
  int g = i / EDGES, le = i - g * EDGES;
  int d = edges[(size_t)g * 2 * EDGES + EDGES + le];
  atomicAdd(&deg5[g * NNODE + d], 1);
}

__global__ void k_scan5(const int* __restrict__ deg5, int* rowptr5) {
  int g = blockIdx.x;
  const int* deg = deg5 + g * NNODE;
  int* rowptr = rowptr5 + g * (NNODE + 1);
  __shared__ int sh[1024];
  __shared__ int srun;
  if (threadIdx.x == 0) srun = 0;
  __syncthreads();
  for (int base = 0; base < NNODE; base += 1024) {
    int i = base + threadIdx.x;
    int v = (i < NNODE) ? deg[i] : 0;
    sh[threadIdx.x] = v;
    __syncthreads();
    for (int off = 1; off < 1024; off <<= 1) {
      int t = 0;
      if (threadIdx.x >= off) t = sh[threadIdx.x - off];
      __syncthreads();
      sh[threadIdx.x] += t;
      __syncthreads();
    }
    int r0 = srun;
    if (i < NNODE) rowptr[i] = r0 + sh[threadIdx.x] - v;
    __syncthreads();
    if (threadIdx.x == 0) srun = r0 + sh[1023];
    __syncthreads();
  }
  if (threadIdx.x == 0) rowptr[NNODE] = srun;
}

__global__ void k_scatter5(const int* __restrict__ edges, const int* __restrict__ rowptr5,
                           int* fill5, int* esrc5, int* eid5) {
  int i = blockIdx.x * 256 + threadIdx.x;
  if (i >= TT * EDGES) return;
  int g = i / EDGES, le = i - g * EDGES;
  const int* src = edges + (size_t)g * 2 * EDGES;
  int t = src[EDGES + le];
  int p = rowptr5[g * (NNODE + 1) + t] + atomicAdd(&fill5[g * NNODE + t], 1);
  esrc5[g * EDGES + p] = src[le];
  eid5[g * EDGES + p] = le;
}

// ------------------------------------------------------------------
// per-node attention dots (clf conv only)
// ------------------------------------------------------------------
__global__ void k_dots(const float* __restrict__ hbuf, const float* __restrict__ asrc,
                       const float* __restrict__ adst, float* dsrc, float* ddst) {
  int n = blockIdx.x;
  int hh = threadIdx.x >> 5, lane = threadIdx.x & 31;
  float v = hbuf[(size_t)n * DIM + threadIdx.x];
  float a = v * asrc[hh * HD + lane];
  float b = v * adst[hh * HD + lane];
#pragma unroll
  for (int o = 16; o; o >>= 1) {
    a += __shfl_xor_sync(0xffffffffu, a, o);
    b += __shfl_xor_sync(0xffffffffu, b, o);
  }
  if (lane == 0) {
    dsrc[n * NH + hh] = a;
    ddst[n * NH + hh] = b;
  }
}

// ------------------------------------------------------------------
// fused segment softmax + aggregation (batched over graphs via grid)
// ------------------------------------------------------------------
template <bool CLF>
__global__ void k_aggregate(const int* __restrict__ rowptr5, const int* __restrict__ esrc5,
                            const int* __restrict__ eid5, const float* __restrict__ hbuf,
                            const float* __restrict__ dsrc, const float* __restrict__ ddst,
                            float* __restrict__ out, float* __restrict__ atts,
                            int* __restrict__ argm) {
  __shared__ float sm[NH], ss[NH];
  __shared__ float redf[256];
  __shared__ int redi[256];
  int idx = blockIdx.x;
  int g = idx / NNODE, node = idx - g * NNODE;
  int tid = threadIdx.x, hh = tid >> 5, lane = tid & 31;
  const int* rowptr = rowptr5 + g * (NNODE + 1);
  const int* esrc = esrc5 + (size_t)g * EDGES;
  int r0 = rowptr[node], r1 = rowptr[node + 1];
  if (r0 == r1) {
    out[(size_t)idx * DIM + tid] = 0.f;
    if (CLF && tid == 0) argm[node] = 0x7fffffff;
    return;
  }
  const float* dsrcg = dsrc + (size_t)g * NNODE * NH;
  float dd = ddst[(size_t)idx * NH + hh];
  float m = -__int_as_float(0x7f800000);
  for (int p = r0 + lane; p < r1; p += 32) {
    int s = esrc[p];
    float v = dsrcg[s * NH + hh] + dd;
    v = v > 0.f ? v : 0.2f * v;
    m = fmaxf(m, v);
  }
#pragma unroll
  for (int o = 16; o; o >>= 1) m = fmaxf(m, __shfl_xor_sync(0xffffffffu, m, o));

  const float* hbg = hbuf + (size_t)g * NNODE * DIM;
  float acc = 0.f, ssum = 0.f;
  for (int pb = r0; pb < r1; pb += 32) {
    int p = pb + lane;
    float ex = 0.f;
    int s = 0;
    if (p < r1) {
      s = esrc[p];
      float v = dsrcg[s * NH + hh] + dd;
      v = v > 0.f ? v : 0.2f * v;
      ex = expf(v - m);
    }
    int cnt = min(32, r1 - pb);
    for (int j = 0; j < cnt; j++) {
      float exj = __shfl_sync(0xffffffffu, ex, j);
      int sj = __shfl_sync(0xffffffffu, s, j);
      acc += exj * hbg[(size_t)sj * DIM + hh * HD + lane];
      ssum += exj;
    }
  }
  out[(size_t)idx * DIM + hh * HD + lane] = acc / (ssum + 1e-16f);

  if (CLF) {
    if (lane == 0) {
      sm[hh] = m;
      ss[hh] = ssum;
    }
    __syncthreads();
    float lmax = -__int_as_float(0x7f800000);
    for (int p = r0 + tid; p < r1; p += 256) {
      int s = esrc[p];
      float att = 0.f;
#pragma unroll
      for (int h2 = 0; h2 < NH; h2++) {
        float v = dsrcg[s * NH + h2] + ddst[(size_t)idx * NH + h2];
        v = v > 0.f ? v : 0.2f * v;
        att += expf(v - sm[h2]) / (ss[h2] + 1e-16f);
      }
      atts[p] = att;
      lmax = fmaxf(lmax, att);
    }
    redf[tid] = lmax;
    __syncthreads();
    for (int o = 128; o; o >>= 1) {
      if (tid < o) redf[tid] = fmaxf(redf[tid], redf[tid + o]);
      __syncthreads();
    }
    float bmax = redf[0];
    int lmin = 0x7fffffff;
    for (int p = r0 + tid; p < r1; p += 256)
      if (atts[p] == bmax) lmin = min(lmin, eid5[p]);
    redi[tid] = lmin;
    __syncthreads();
    for (int o = 128; o; o >>= 1) {
      if (tid < o) redi[tid] = min(redi[tid], redi[tid + o]);
      __syncthreads();
    }
    if (tid == 0) argm[node] = redi[0];
  }
}

// ------------------------------------------------------------------
// LSTM prep / step / pooling
// ------------------------------------------------------------------
__global__ void k_gather5(const float* __restrict__ aggB, const int* __restrict__ nbrs,
                          float* __restrict__ x, int* __restrict__ flag) {
  __shared__ int s;
  int n = blockIdx.x, g = blockIdx.y, d = threadIdx.x;
  int t = TT - 1 - g;
  if (d == 0) s = 0;
  __syncthreads();
  float v = aggB[((size_t)g * NNODE + nbrs[n]) * DIM + d];
  x[(size_t)n * TT * DIM + t * DIM + d] = v;
  if (v != 0.f) s = 1;
  __syncthreads();
  if (d == 0) flag[n * TT + t] = s;
}

__global__ void k_lens(const int* __restrict__ flag, int* lens, int* maxlen) {
  int n = blockIdx.x * 256 + threadIdx.x;
  if (n >= BNB) return;
  int c = 0;
#pragma unroll
  for (int t = 0; t < TT; t++) c += flag[n * TT + t];
  lens[n] = c;
  atomicMax(maxlen, c);
}

__global__ void k_buildrev(const float* __restrict__ x, const int* __restrict__ lens,
                           float* __restrict__ xrev) {
  int i = blockIdx.x * 256 + threadIdx.x;
  if (i >= BNB * TT * DIM) return;
  int d = i & (DIM - 1);
  int nt = i / DIM;
  int t = nt % TT, n = nt / TT;
  int idx = lens[n] - 1 - t;
  idx = max(0, min(idx, TT - 1));
  xrev[i] = x[(size_t)n * TT * DIM + idx * DIM + d];
}

// batched fwd+bwd: rr in [0, 2*BNB)
__global__ void k_lstmstep(const float* __restrict__ G, int t, float* __restrict__ h,
                           float* __restrict__ c, float* __restrict__ hs) {
  int rr = blockIdx.x, d = threadIdx.x;
  const float* g = G + (size_t)rr * (TT * GD) + t * GD;
  float gi = g[d], gf = g[DIM + d], gg = g[2 * DIM + d], go = g[3 * DIM + d];
  float cc = sigmf(gf) * c[rr * DIM + d] + sigmf(gi) * tanhf(gg);
  float hh = sigmf(go) * tanhf(cc);
  c[rr * DIM + d] = cc;
  h[rr * DIM + d] = hh;
  hs[(size_t)rr * TT * DIM + t * DIM + d] = hh;
}

__global__ void k_pool(const float* __restrict__ hs, const int* __restrict__ lens,
                       const int* __restrict__ maxlen, float* __restrict__ pooled) {
  int n = blockIdx.x, d = threadIdx.x;
  int ln = lens[n];
  float inv = 1.0f / (float)max(*maxlen, 1);
  const float* hsf = hs;
  const float* hsb = hs + (size_t)BNB * TT * DIM;
  float s = 0.f;
  for (int t = 0; t < ln; t++) {
    float f = hsf[(size_t)n * TT * DIM + t * DIM + d];
    float bb = hsb[(size_t)n * TT * DIM + (ln - 1 - t) * DIM + d];
    s += 0.5f * (f + bb);
  }
  pooled[n * DIM + d] = s * inv;
}

// ------------------------------------------------------------------
// clf helpers + head
// ------------------------------------------------------------------
__global__ void k_fillbias(const float* __restrict__ b, float* __restrict__ hbuf) {
  int n = blockIdx.x, d = threadIdx.x;
  hbuf[(size_t)n * DIM + d] = b[d];
}

__global__ void k_scatrows(const float* __restrict__ src, const int* __restrict__ idx,
                           float* __restrict__ dst) {
  int n = blockIdx.x, d = threadIdx.x;
  dst[(size_t)idx[n] * DIM + d] = src[(size_t)n * DIM + d];
}

__global__ void k_gatherrows(const float* __restrict__ src, const int* __restrict__ idx,
                             float* __restrict__ dst) {
  int n = blockIdx.x, d = threadIdx.x;
  dst[(size_t)n * DIM + d] = src[(size_t)idx[n] * DIM + d];
}

__global__ void k_mlp(const float* __restrict__ hclf, const float* __restrict__ scl,
                      const float* __restrict__ sft, const float* __restrict__ W1,
                      const float* __restrict__ b1, const float* __restrict__ W2,
                      const float* __restrict__ b2, const float* __restrict__ W3,
                      const float* __restrict__ b3, float* __restrict__ out, int out_size) {
  __shared__ float hrow[256], p1[32], p2[16];
  int i = blockIdx.x, tid = threadIdx.x;
  for (int k = tid; k < 256; k += 64) hrow[k] = hclf[(size_t)i * DIM + k] * scl[k] + sft[k];
  __syncthreads();
  if (tid < 32) {
    float s = b1[tid];
    for (int k = 0; k < 256; k++) s += hrow[k] * W1[k * 32 + tid];
    p1[tid] = tanhf(s);
  }
  __syncthreads();
  if (tid < 16) {
    float s = b2[tid];
    for (int k = 0; k < 32; k++) s += p1[k] * W2[k * 16 + tid];
    p2[tid] = tanhf(s);
  }
  __syncthreads();
  if (tid == 0) {
    float s = b3[0];
    for (int k = 0; k < 16; k++) s += p2[k] * W3[k];
    if (i < out_size) out[i] = 1.f / (1.f + expf(-s));
  }
}

__global__ void k_srcsel(const int* __restrict__ argm, const int* __restrict__ clf_nodes,
                         const int* __restrict__ src4, float* __restrict__ out, int out_size) {
  int i = blockIdx.x * 256 + threadIdx.x;
  if (i >= BCB) return;
  int a = argm[clf_nodes[i]];
  a = max(0, min(a, EDGES - 1));
  if (BCB + i < out_size) out[BCB + i] = (float)src4[a];
}

// ------------------------------------------------------------------
// host orchestration
// ------------------------------------------------------------------
extern "C" void kernel_launch(void* const* d_in, const int* in_sizes, int n_in, void* d_out,
                              int out_size) {
  static Scratch* sp = nullptr;
  if (!sp) {
    void* p = nullptr;
    cudaGetSymbolAddress(&p, S);
    sp = (Scratch*)p;
  }
  const float* emb = (const float*)d_in[0];
  const int* edges = (const int*)d_in[1];
  const int* clf_neighbors = (const int*)d_in[4];
  const int* clf_nodes = (const int*)d_in[5];
  const float* bn1_g = (const float*)d_in[6];
  const float* bn1_b = (const float*)d_in[7];
  const float* gnn_W = (const float*)d_in[8];
  const float* gnn_b = (const float*)d_in[9];
  const float* gnn_asrc = (const float*)d_in[10];
  const float* gnn_adst = (const float*)d_in[11];
  const float* lstm_Wih = (const float*)d_in[12];
  const float* lstm_Whh = (const float*)d_in[13];
  const float* lstm_bih = (const float*)d_in[14];
  const float* lstm_bhh = (const float*)d_in[15];
  const float* bn2_g = (const float*)d_in[16];
  const float* bn2_b = (const float*)d_in[17];
  const float* clf_W = (const float*)d_in[18];
  const float* clf_b = (const float*)d_in[19];
  const float* clf_asrc = (const float*)d_in[20];
  const float* clf_adst = (const float*)d_in[21];
  const float* W1 = (const float*)d_in[22];
  const float* b1 = (const float*)d_in[23];
  const float* W2 = (const float*)d_in[24];
  const float* b2 = (const float*)d_in[25];
  const float* W3 = (const float*)d_in[26];
  const float* b3 = (const float*)d_in[27];
  float* out = (float*)d_out;

  const int EB5 = (TT * EDGES + 255) / 256;
  const float MinvN = 1.0f / NNODE;
  const dim3 gBig(2, (TT * NNODE + 127) / 128);
  float* xrev = sp->xx + (size_t)BNB * TT * DIM;

  // 1 splitFT W0, 2 zerof, 3 bnstats, 4 big GEMM (ncu target @ my-4th-launch)
  k_splitFT<<<128, 256>>>(gnn_W, sp->gWh, sp->gWl, DIM);
  k_zerof<<<8, 256>>>(sp->csum5, 2 * TT * DIM);
  k_bnstats5<<<dim3(8, TT, 25), 256>>>(emb, NNODE, sp->csum5, sp->csq5);
  k_mgemm<1><<<gBig, 256>>>(emb, DIM, sp->gWh, sp->gWl, nullptr, nullptr, sp->hbuf, DIM, gnn_b,
                            gnn_b, 1 << 30, sp->csum5, sp->csq5, bn1_g, bn1_b, MinvN, NNODE,
                            gnn_asrc, gnn_adst, sp->dsrc, sp->ddst, TT * NNODE);

  // remaining weight splits + bias prep
  k_splitFT<<<128, 256>>>(gnn_W + DIM * DIM, sp->gWh + DIM * 128, sp->gWl + DIM * 128, DIM);
  k_splitFT<<<128, 256>>>(clf_W, sp->cWh, sp->cWl, DIM);
  k_splitFD<<<1024, 256>>>(lstm_Wih, sp->wihh, sp->wihl, 2 * GD);
  k_splitFD<<<1024, 256>>>(lstm_Whh, sp->whhh, sp->whhl, 2 * GD);
  k_addb<<<(2 * GD + 255) / 256, 256>>>(lstm_bih, lstm_bhh, sp->bias2, 2 * GD);

  // CSR for all 5 graphs
  k_zeroi<<<120, 256>>>(sp->deg5, TT * NNODE);
  k_zeroi<<<120, 256>>>(sp->fill5, TT * NNODE);
  k_count5<<<EB5, 256>>>(edges, sp->deg5);
  k_scan5<<<TT, 1024>>>(sp->deg5, sp->rowptr5);
  k_scatter5<<<EB5, 256>>>(edges, sp->rowptr5, sp->fill5, sp->esrc5, sp->eid5);

  // layer 0 aggregate
  k_aggregate<false><<<TT * NNODE, 256>>>(sp->rowptr5, sp->esrc5, sp->eid5, sp->hbuf, sp->dsrc,
                                          sp->ddst, sp->aggA, nullptr, nullptr);

  // layer 1
  k_zerof<<<8, 256>>>(sp->csum5, 2 * TT * DIM);
  k_bnstats5<<<dim3(8, TT, 25), 256>>>(sp->aggA, NNODE, sp->csum5, sp->csq5);
  k_mgemm<1><<<gBig, 256>>>(sp->aggA, DIM, sp->gWh + DIM * 128, sp->gWl + DIM * 128, nullptr,
                            nullptr, sp->hbuf, DIM, gnn_b + DIM, gnn_b + DIM, 1 << 30, sp->csum5,
                            sp->csq5, bn1_g, bn1_b, MinvN, NNODE, gnn_asrc + NH * HD,
                            gnn_adst + NH * HD, sp->dsrc, sp->ddst, TT * NNODE);
  k_aggregate<false><<<TT * NNODE, 256>>>(sp->rowptr5, sp->esrc5, sp->eid5, sp->hbuf, sp->dsrc,
                                          sp->ddst, sp->aggB, nullptr, nullptr);

  // sequences (graph g -> time step TT-1-g)
  k_gather5<<<dim3(BNB, TT), 256>>>(sp->aggB, clf_neighbors, sp->xx, sp->flag);
  k_zeroi<<<1, 32>>>(&sp->maxlen, 1);
  k_lens<<<(BNB + 255) / 256, 256>>>(sp->flag, sp->lens, &sp->maxlen);
  k_buildrev<<<(BNB * TT * DIM + 255) / 256, 256>>>(sp->xx, sp->lens, xrev);

  // batched bi-LSTM: input GEMM (fwd rows < 20480, bwd rows >= 20480)
  k_mgemm<0><<<dim3(8, (2 * BNB * TT) / 128), 256>>>(
      sp->xx, DIM, sp->wihh, sp->wihl, sp->wihh + GD * 128, sp->wihl + GD * 128, sp->Gpre, GD,
      sp->bias2, sp->bias2 + GD, BNB * TT, nullptr, nullptr, nullptr, nullptr, 0.f, 0, nullptr,
      nullptr, nullptr, nullptr, 2 * BNB * TT);
  k_zerof<<<(4 * BNB * DIM + 255) / 256, 256>>>(sp->h, 4 * BNB * DIM);  // h and c adjacent
  for (int t = 0; t < TT; t++) {
    k_mgemm<2><<<dim3(8, (2 * BNB) / 128), 256>>>(
        sp->h, DIM, sp->whhh, sp->whhl, sp->whhh + GD * 128, sp->whhl + GD * 128,
        sp->Gpre + t * GD, TT * GD, nullptr, nullptr, BNB, nullptr, nullptr, nullptr, nullptr,
        0.f, 0, nullptr, nullptr, nullptr, nullptr, 2 * BNB);
    k_lstmstep<<<2 * BNB, 256>>>(sp->Gpre, t, sp->h, sp->c, sp->hs);
  }
  k_pool<<<BNB, 256>>>(sp->hs, sp->lens, &sp->maxlen, sp->pooled);

  // clf conv (CSR of graph 4 reused)
  const int* src4 = edges + (size_t)(TT - 1) * 2 * EDGES;
  k_fillbias<<<NNODE, 256>>>(clf_b, sp->clfH);
  k_mgemm<0><<<dim3(2, BNB / 128), 256>>>(
      sp->pooled, DIM, sp->cWh, sp->cWl, nullptr, nullptr, sp->xx, DIM, clf_b, clf_b, 1 << 30,
      nullptr, nullptr, nullptr, nullptr, 0.f, 0, nullptr, nullptr, nullptr, nullptr, BNB);
  k_scatrows<<<BNB, 256>>>(sp->xx, clf_neighbors, sp->clfH);
  k_dots<<<NNODE, 256>>>(sp->clfH, clf_asrc, clf_adst, sp->dsrcC, sp->ddstC);
  k_aggregate<true><<<NNODE, 256>>>(sp->rowptr5 + 4 * (NNODE + 1), sp->esrc5 + 4 * EDGES,
                                    sp->eid5 + 4 * EDGES, sp->clfH, sp->dsrcC, sp->ddstC,
                                    sp->aggA, sp->atts, sp->argm);

  // head
  k_gatherrows<<<BCB, 256>>>(sp->aggA, clf_nodes, sp->hclf);
  k_zerof<<<8, 256>>>(sp->csum5, 2 * TT * DIM);
  k_bnstats5<<<dim3(8, 1, 4), 256>>>(sp->hclf, BCB, sp->csum5, sp->csq5);
  k_bnfin5<<<1, 256>>>(sp->csum5, sp->csq5, bn2_g, bn2_b, 1.0f / BCB, sp->scl5, sp->sft5);
  k_mlp<<<BCB, 64>>>(sp->hclf, sp->scl5, sp->sft5, W1, b1, W2, b2, W3, b3, out, out_size);
  k_srcsel<<<(BCB + 255) / 256, 256>>>(sp->argm, clf_nodes, src4, out, out_size);
}

// round 15
// speedup vs baseline: 1.1041x; 1.1041x over previous
#include <cuda_runtime.h>
#include <cuda_bf16.h>
#include <math.h>
#include <stdint.h>

#define TT 5
#define NNODE 20000
#define EDGES 320000
#define DIM 256
#define NH 8
#define HD 32
#define BNB 4096
#define BCB 2048
#define GD 1024 /* 4*DIM */

// ------------------------------------------------------------------
// Static device scratch (no allocations allowed anywhere).
// ------------------------------------------------------------------
struct Scratch {
  alignas(16) float dsrc[TT * NNODE * NH];
  alignas(16) float ddst[TT * NNODE * NH];
  alignas(16) float csum5[TT * DIM];
  alignas(16) float csq5[TT * DIM];
  alignas(16) float scl5[TT * DIM];
  alignas(16) float sft5[TT * DIM];
  alignas(16) float hbuf[TT * NNODE * DIM];
  alignas(16) float aggA[TT * NNODE * DIM];
  alignas(16) float aggB[TT * NNODE * DIM];
  alignas(16) float clfH[NNODE * DIM];
  alignas(16) float dsrcC[NNODE * NH];
  alignas(16) float ddstC[NNODE * NH];
  alignas(16) int   deg5[TT * NNODE];
  alignas(16) int   fill5[TT * NNODE];
  alignas(16) int   rowptr5[TT * (NNODE + 1)];
  alignas(16) int   esrc5[TT * EDGES];
  alignas(16) int   eid5[TT * EDGES];
  alignas(16) float atts[EDGES];
  alignas(16) int   argm[NNODE];
  alignas(16) float xx[2 * BNB * TT * DIM];   // [0]=x fwd, [1]=xrev
  alignas(16) int   flag[BNB * TT];
  alignas(16) int   lens[BNB];
  alignas(16) int   maxlen;
  alignas(16) float Gpre[2 * BNB * TT * GD];  // fwd half, bwd half
  alignas(16) float h[2 * BNB * DIM];         // keep h,c adjacent (joint zero)
  alignas(16) float c[2 * BNB * DIM];
  alignas(16) float hs[2 * BNB * TT * DIM];   // hsf then hsb
  alignas(16) float pooled[BNB * DIM];
  alignas(16) float bias2[2 * GD];
  alignas(16) float hclf[BCB * DIM];
  // fragment-ready bf16 splits of B operands (u32 = 2 packed bf16)
  alignas(16) uint32_t gWh[2 * DIM * 128];
  alignas(16) uint32_t gWl[2 * DIM * 128];
  alignas(16) uint32_t cWh[DIM * 128];
  alignas(16) uint32_t cWl[DIM * 128];
  alignas(16) uint32_t wihh[2 * GD * 128];
  alignas(16) uint32_t wihl[2 * GD * 128];
  alignas(16) uint32_t whhh[2 * GD * 128];
  alignas(16) uint32_t whhl[2 * GD * 128];
};
__device__ Scratch S;

__device__ __forceinline__ float sigmf(float x) { return 1.f / (1.f + expf(-x)); }

// ------------------------------------------------------------------
// mma helpers
// ------------------------------------------------------------------
__device__ __forceinline__ void ldsm4(uint32_t& r0, uint32_t& r1, uint32_t& r2, uint32_t& r3,
                                      const void* p) {
  uint32_t a = (uint32_t)__cvta_generic_to_shared(p);
  asm volatile("ldmatrix.sync.aligned.m8n8.x4.shared.b16 {%0,%1,%2,%3}, [%4];"
               : "=r"(r0), "=r"(r1), "=r"(r2), "=r"(r3) : "r"(a));
}
__device__ __forceinline__ void mma16816(float* d, const uint32_t* a, const uint32_t* b) {
  asm volatile(
      "mma.sync.aligned.m16n8k16.row.col.f32.bf16.bf16.f32 "
      "{%0,%1,%2,%3}, {%4,%5,%6,%7}, {%8,%9}, {%0,%1,%2,%3};"
      : "+f"(d[0]), "+f"(d[1]), "+f"(d[2]), "+f"(d[3])
      : "r"(a[0]), "r"(a[1]), "r"(a[2]), "r"(a[3]), "r"(b[0]), "r"(b[1]));
}
__device__ __forceinline__ void split2(float x, unsigned short& h, unsigned short& l) {
  __nv_bfloat16 hb = __float2bfloat16(x);
  h = __bfloat16_as_ushort(hb);
  l = __bfloat16_as_ushort(__float2bfloat16(x - __bfloat162float(hb)));
}

// ------------------------------------------------------------------
// utilities
// ------------------------------------------------------------------
__global__ void k_zerof(float* p, int n) {
  for (int i = blockIdx.x * blockDim.x + threadIdx.x; i < n; i += gridDim.x * blockDim.x) p[i] = 0.f;
}
__global__ void k_zeroi(int* p, int n) {
  for (int i = blockIdx.x * blockDim.x + threadIdx.x; i < n; i += gridDim.x * blockDim.x) p[i] = 0;
}

// ------------------------------------------------------------------
// fragment-ready weight splits (K = 256 fixed).
// layout: u32 idx = ((n8*16 + k16)*2 + r)*32 + lane
// content: pack(B[n8*8 + lane/4][k16*16 + r*8 + 2*(lane&3)], same+1)
// ------------------------------------------------------------------
__global__ void k_splitFT(const float* __restrict__ W /*[K=256][N]*/, uint32_t* oh, uint32_t* ol,
                          int N) {
  int i = blockIdx.x * 256 + threadIdx.x;  // over N*128
  if (i >= N * 128) return;
  int l = i & 31, r = (i >> 5) & 1, k16 = (i >> 6) & 15, n8 = i >> 10;
  int n = n8 * 8 + (l >> 2);
  int k = k16 * 16 + r * 8 + 2 * (l & 3);
  float s0 = W[(size_t)k * N + n];
  float s1 = W[(size_t)(k + 1) * N + n];
  unsigned short h0, l0, h1, l1;
  split2(s0, h0, l0);
  split2(s1, h1, l1);
  oh[i] = (uint32_t)h0 | ((uint32_t)h1 << 16);
  ol[i] = (uint32_t)l0 | ((uint32_t)l1 << 16);
}
__global__ void k_splitFD(const float* __restrict__ W /*[N][K=256]*/, uint32_t* oh, uint32_t* ol,
                          int N) {
  int i = blockIdx.x * 256 + threadIdx.x;
  if (i >= N * 128) return;
  int l = i & 31, r = (i >> 5) & 1, k16 = (i >> 6) & 15, n8 = i >> 10;
  int n = n8 * 8 + (l >> 2);
  int k = k16 * 16 + r * 8 + 2 * (l & 3);
  float s0 = W[(size_t)n * 256 + k];
  float s1 = W[(size_t)n * 256 + k + 1];
  unsigned short h0, l0, h1, l1;
  split2(s0, h0, l0);
  split2(s1, h1, l1);
  oh[i] = (uint32_t)h0 | ((uint32_t)h1 << 16);
  ol[i] = (uint32_t)l0 | ((uint32_t)l1 << 16);
}

__global__ void k_addb(const float* a, const float* b, float* o, int n) {
  int i = blockIdx.x * 256 + threadIdx.x;
  if (i < n) o[i] = a[i] + b[i];
}

// ------------------------------------------------------------------
// BN stats (chunked) + finalize (head only)
// ------------------------------------------------------------------
__global__ void k_bnstats5(const float* __restrict__ x, int M, float* csum, float* csq) {
  __shared__ float sh[2][8][32];
  int g = blockIdx.y;
  int lane = threadIdx.x & 31, rth = threadIdx.x >> 5;
  int col = blockIdx.x * 32 + lane;
  int nch = gridDim.z, ch = blockIdx.z;
  int r0 = (int)(((long long)M * ch) / nch), r1 = (int)(((long long)M * (ch + 1)) / nch);
  const float* xg = x + (size_t)g * M * DIM;
  float s = 0.f, q = 0.f;
  for (int r = r0 + rth; r < r1; r += 8) {
    float v = xg[(size_t)r * DIM + col];
    s += v;
    q += v * v;
  }
  sh[0][rth][lane] = s;
  sh[1][rth][lane] = q;
  __syncthreads();
  if (rth == 0) {
#pragma unroll
    for (int i = 1; i < 8; i++) {
      s += sh[0][i][lane];
      q += sh[1][i][lane];
    }
    atomicAdd(&csum[g * DIM + col], s);
    atomicAdd(&csq[g * DIM + col], q);
  }
}

__global__ void k_bnfin5(const float* csum, const float* csq, const float* __restrict__ g,
                         const float* __restrict__ b, float Minv, float* scl, float* sft) {
  int gg = blockIdx.x, d = threadIdx.x;
  float mu = csum[gg * DIM + d] * Minv;
  float var = csq[gg * DIM + d] * Minv - mu * mu;
  float rs = rsqrtf(var + 1e-5f);
  float sc = g[d] * rs;
  scl[gg * DIM + d] = sc;
  sft[gg * DIM + d] = b[d] - mu * sc;
}

// ------------------------------------------------------------------
// HMMA split-bf16 GEMM (R13-proven). A double-buffered in smem; B fragments
// loaded directly from global in fragment-ready layout.
// MODE 0: +bias. MODE 1: BN on A + bias + fused per-head dots. MODE 2: accum.
// Rows >= Msplit use (Bh2,Bl2,biasB).
// ------------------------------------------------------------------
#define SPITCH 24
#define STILE (128 * SPITCH * 2) /* bytes per bf16 tile: 6144 */

template <int MODE>
__device__ __forceinline__ void stage_store(char* dyn, int s, int sr, int sc, float4 f0,
                                            float4 f1, const float* __restrict__ csum,
                                            const float* __restrict__ csq,
                                            const float* __restrict__ gma,
                                            const float* __restrict__ bta, float Minv, int gbase,
                                            int cbase) {
  float v[8] = {f0.x, f0.y, f0.z, f0.w, f1.x, f1.y, f1.z, f1.w};
  if (MODE == 1) {
#pragma unroll
    for (int j = 0; j < 8; j++) {
      int cc = cbase + j;
      float mu = csum[gbase + cc] * Minv;
      float var = csq[gbase + cc] * Minv - mu * mu;
      float scv = gma[cc] * rsqrtf(var + 1e-5f);
      v[j] = v[j] * scv + (bta[cc] - mu * scv);
    }
  }
  unsigned short hsv[8], lsv[8];
#pragma unroll
  for (int j = 0; j < 8; j++) split2(v[j], hsv[j], lsv[j]);
  uint4 pa, pl;
  pa.x = (uint32_t)hsv[0] | ((uint32_t)hsv[1] << 16);
  pa.y = (uint32_t)hsv[2] | ((uint32_t)hsv[3] << 16);
  pa.z = (uint32_t)hsv[4] | ((uint32_t)hsv[5] << 16);
  pa.w = (uint32_t)hsv[6] | ((uint32_t)hsv[7] << 16);
  pl.x = (uint32_t)lsv[0] | ((uint32_t)lsv[1] << 16);
  pl.y = (uint32_t)lsv[2] | ((uint32_t)lsv[3] << 16);
  pl.z = (uint32_t)lsv[4] | ((uint32_t)lsv[5] << 16);
  pl.w = (uint32_t)lsv[6] | ((uint32_t)lsv[7] << 16);
  size_t off = (size_t)s * STILE + sr * (SPITCH * 2) + sc * 2;
  *(uint4*)(dyn + off) = pa;
  *(uint4*)(dyn + 2 * STILE + off) = pl;
}

template <int MODE>
__global__ __launch_bounds__(256, 2) void k_mgemm(
    const float* __restrict__ A, int lda, const uint32_t* __restrict__ Bh_g,
    const uint32_t* __restrict__ Bl_g, const uint32_t* __restrict__ Bh2_g,
    const uint32_t* __restrict__ Bl2_g, float* __restrict__ C, int ldc,
    const float* __restrict__ bias, const float* __restrict__ biasB, int Msplit,
    const float* __restrict__ csum, const float* __restrict__ csq,
    const float* __restrict__ gma, const float* __restrict__ bta, float Minv, int nper,
    const float* __restrict__ asrc, const float* __restrict__ adst, float* __restrict__ dsrc,
    float* __restrict__ ddst, int M) {
  __shared__ __align__(16) char dyn[4 * STILE];  // 24KB: Ah,Al x 2 stages
  const int tid = threadIdx.x, lane = tid & 31, wid = tid >> 5;
  const int wm = wid & 3, wn = wid >> 2;
  const int row0 = blockIdx.y * 128, col0 = blockIdx.x * 128;
  const bool second = (row0 >= Msplit);
  const uint32_t* BhU = second ? Bh2_g : Bh_g;
  const uint32_t* BlU = second ? Bl2_g : Bl_g;
  const float* biasU = second ? biasB : bias;

  float acc[2][8][4];
#pragma unroll
  for (int i = 0; i < 2; i++)
#pragma unroll
    for (int j = 0; j < 8; j++)
#pragma unroll
      for (int q = 0; q < 4; q++) acc[i][j][q] = 0.f;

  int arow = row0 + (tid >> 1);
  if (arow >= M) arow = M - 1;
  const int sc = (tid & 1) * 8;
  const float* Ap = A + (size_t)arow * lda + sc;
  int gbase = (MODE == 1) ? (arow / nper) * DIM : 0;
  const int sr = tid >> 1;
  const int n8w = (col0 + wn * 64) >> 3;

  {
    float4 f0 = *(const float4*)(Ap);
    float4 f1 = *(const float4*)(Ap + 4);
    stage_store<MODE>(dyn, 0, sr, sc, f0, f1, csum, csq, gma, bta, Minv, gbase, sc);
  }
  float4 pf0 = *(const float4*)(Ap + 16);
  float4 pf1 = *(const float4*)(Ap + 20);
  __syncthreads();

  for (int kc = 0; kc < 256; kc += 16) {
    const int s = (kc >> 4) & 1;
    const int k16 = kc >> 4;
    char* base = dyn + (size_t)s * STILE;
    uint32_t ah[2][4], al[2][4];
#pragma unroll
    for (int mt = 0; mt < 2; mt++) {
      int r = wm * 32 + mt * 16 + (lane & 15);
      int half = (lane >> 4) * 8;
      ldsm4(ah[mt][0], ah[mt][1], ah[mt][2], ah[mt][3], base + r * (SPITCH * 2) + half * 2);
      ldsm4(al[mt][0], al[mt][1], al[mt][2], al[mt][3],
            base + 2 * STILE + r * (SPITCH * 2) + half * 2);
    }
    if (kc + 16 < 256) {
      stage_store<MODE>(dyn, s ^ 1, sr, sc, pf0, pf1, csum, csq, gma, bta, Minv, gbase,
                        kc + 16 + sc);
      if (kc + 32 < 256) {
        pf0 = *(const float4*)(Ap + kc + 32);
        pf1 = *(const float4*)(Ap + kc + 36);
      }
    }
#pragma unroll
    for (int np = 0; np < 4; np++) {
      int n8 = n8w + np * 2;
      int idx0 = (n8 * 16 + k16) * 64 + lane;
      uint32_t bh[4], bl[4];
      bh[0] = BhU[idx0];
      bh[1] = BhU[idx0 + 32];
      bh[2] = BhU[idx0 + 1024];
      bh[3] = BhU[idx0 + 1056];
      bl[0] = BlU[idx0];
      bl[1] = BlU[idx0 + 32];
      bl[2] = BlU[idx0 + 1024];
      bl[3] = BlU[idx0 + 1056];
      mma16816(acc[0][2 * np], ah[0], bh);
      mma16816(acc[1][2 * np], ah[1], bh);
      mma16816(acc[0][2 * np + 1], ah[0], bh + 2);
      mma16816(acc[1][2 * np + 1], ah[1], bh + 2);
      mma16816(acc[0][2 * np], ah[0], bl);
      mma16816(acc[1][2 * np], ah[1], bl);
      mma16816(acc[0][2 * np + 1], ah[0], bl + 2);
      mma16816(acc[1][2 * np + 1], ah[1], bl + 2);
      mma16816(acc[0][2 * np], al[0], bh);
      mma16816(acc[1][2 * np], al[1], bh);
      mma16816(acc[0][2 * np + 1], al[0], bh + 2);
      mma16816(acc[1][2 * np + 1], al[1], bh + 2);
    }
    __syncthreads();
  }

  // ---- epilogue ----
  const int qlane = lane & 3;
  const int hA = (col0 + wn * 64) >> 5;
#pragma unroll
  for (int mt = 0; mt < 2; mt++) {
    int r = row0 + wm * 32 + mt * 16 + (lane >> 2);
    float dA0[2] = {0.f, 0.f}, dA1[2] = {0.f, 0.f};
    float dB0[2] = {0.f, 0.f}, dB1[2] = {0.f, 0.f};
#pragma unroll
    for (int nt = 0; nt < 8; nt++) {
      int cloc = wn * 64 + nt * 8 + qlane * 2;
      float b0 = 0.f, b1 = 0.f;
      if (MODE != 2 && biasU) {
        b0 = biasU[col0 + cloc];
        b1 = biasU[col0 + cloc + 1];
      }
      float c0 = acc[mt][nt][0] + b0, c1 = acc[mt][nt][1] + b1;
      float c2 = acc[mt][nt][2] + b0, c3 = acc[mt][nt][3] + b1;
      size_t off0 = (size_t)r * ldc + col0 + cloc;
      size_t off8 = off0 + (size_t)8 * ldc;
      if (MODE == 2) {
        if (r < M) {
          float2 o = *(const float2*)(C + off0);
          c0 += o.x;
          c1 += o.y;
        }
        if (r + 8 < M) {
          float2 o = *(const float2*)(C + off8);
          c2 += o.x;
          c3 += o.y;
        }
      }
      if (r < M) *(float2*)(C + off0) = make_float2(c0, c1);
      if (r + 8 < M) *(float2*)(C + off8) = make_float2(c2, c3);
      if (MODE == 1) {
        int hh = nt >> 2;
        float as0 = asrc[col0 + cloc], as1 = asrc[col0 + cloc + 1];
        float ad0 = adst[col0 + cloc], ad1 = adst[col0 + cloc + 1];
        dA0[hh] += c0 * as0 + c1 * as1;
        dA1[hh] += c2 * as0 + c3 * as1;
        dB0[hh] += c0 * ad0 + c1 * ad1;
        dB1[hh] += c2 * ad0 + c3 * ad1;
      }
    }
    if (MODE == 1) {
#pragma unroll
      for (int off = 1; off <= 2; off <<= 1) {
#pragma unroll
        for (int hh = 0; hh < 2; hh++) {
          dA0[hh] += __shfl_xor_sync(0xffffffffu, dA0[hh], off);
          dA1[hh] += __shfl_xor_sync(0xffffffffu, dA1[hh], off);
          dB0[hh] += __shfl_xor_sync(0xffffffffu, dB0[hh], off);
          dB1[hh] += __shfl_xor_sync(0xffffffffu, dB1[hh], off);
        }
      }
      if (qlane == 0) {
        if (r < M) {
          dsrc[(size_t)r * NH + hA] = dA0[0];
          dsrc[(size_t)r * NH + hA + 1] = dA0[1];
          ddst[(size_t)r * NH + hA] = dB0[0];
          ddst[(size_t)r * NH + hA + 1] = dB0[1];
        }
        if (r + 8 < M) {
          dsrc[(size_t)(r + 8) * NH + hA] = dA1[0];
          dsrc[(size_t)(r + 8) * NH + hA + 1] = dA1[1];
          ddst[(size_t)(r + 8) * NH + hA] = dB1[0];
          ddst[(size_t)(r + 8) * NH + hA + 1] = dB1[1];
        }
      }
    }
  }
}

// ------------------------------------------------------------------
// CSR build (all 5 graphs)
// ------------------------------------------------------------------
__global__ void k_count5(const int* __restrict__ edges, int* deg5) {
  int i = blockIdx.x * 256 + threadIdx.x;
  if (i >= TT * EDGES) return;
  int g = i / EDGES, le = i - g * EDGES;
  int d = edges[(size_t)g * 2 * EDGES + EDGES + le];
  atomicAdd(&deg5[g * NNODE + d], 1);
}

__global__ void k_scan5(const int* __restrict__ deg5, int* rowptr5) {
  int g = blockIdx.x;
  const int* deg = deg5 + g * NNODE;
  int* rowptr = rowptr5 + g * (NNODE + 1);
  __shared__ int sh[1024];
  __shared__ int srun;
  if (threadIdx.x == 0) srun = 0;
  __syncthreads();
  for (int base = 0; base < NNODE; base += 1024) {
    int i = base + threadIdx.x;
    int v = (i < NNODE) ? deg[i] : 0;
    sh[threadIdx.x] = v;
    __syncthreads();
    for (int off = 1; off < 1024; off <<= 1) {
      int t = 0;
      if (threadIdx.x >= off) t = sh[threadIdx.x - off];
      __syncthreads();
      sh[threadIdx.x] += t;
      __syncthreads();
    }
    int r0 = srun;
    if (i < NNODE) rowptr[i] = r0 + sh[threadIdx.x] - v;
    __syncthreads();
    if (threadIdx.x == 0) srun = r0 + sh[1023];
    __syncthreads();
  }
  if (threadIdx.x == 0) rowptr[NNODE] = srun;
}

__global__ void k_scatter5(const int* __restrict__ edges, const int* __restrict__ rowptr5,
                           int* fill5, int* esrc5, int* eid5) {
  int i = blockIdx.x * 256 + threadIdx.x;
  if (i >= TT * EDGES) return;
  int g = i / EDGES, le = i - g * EDGES;
  const int* src = edges + (size_t)g * 2 * EDGES;
  int t = src[EDGES + le];
  int p = rowptr5[g * (NNODE + 1) + t] + atomicAdd(&fill5[g * NNODE + t], 1);
  esrc5[g * EDGES + p] = src[le];
  eid5[g * EDGES + p] = le;
}

// ------------------------------------------------------------------
// per-node attention dots (clf conv only)
// ------------------------------------------------------------------
__global__ void k_dots(const float* __restrict__ hbuf, const float* __restrict__ asrc,
                       const float* __restrict__ adst, float* dsrc, float* ddst) {
  int n = blockIdx.x;
  int hh = threadIdx.x >> 5, lane = threadIdx.x & 31;
  float v = hbuf[(size_t)n * DIM + threadIdx.x];
  float a = v * asrc[hh * HD + lane];
  float b = v * adst[hh * HD + lane];
#pragma unroll
  for (int o = 16; o; o >>= 1) {
    a += __shfl_xor_sync(0xffffffffu, a, o);
    b += __shfl_xor_sync(0xffffffffu, b, o);
  }
  if (lane == 0) {
    dsrc[n * NH + hh] = a;
    ddst[n * NH + hh] = b;
  }
}

// ------------------------------------------------------------------
// fused segment softmax + aggregation (batched over graphs via grid)
// ------------------------------------------------------------------
template <bool CLF>
__global__ void k_aggregate(const int* __restrict__ rowptr5, const int* __restrict__ esrc5,
                            const int* __restrict__ eid5, const float* __restrict__ hbuf,
                            const float* __restrict__ dsrc, const float* __restrict__ ddst,
                            float* __restrict__ out, float* __restrict__ atts,
                            int* __restrict__ argm) {
  __shared__ float sm[NH], ss[NH];
  __shared__ float redf[256];
  __shared__ int redi[256];
  int idx = blockIdx.x;
  int g = idx / NNODE, node = idx - g * NNODE;
  int tid = threadIdx.x, hh = tid >> 5, lane = tid & 31;
  const int* rowptr = rowptr5 + g * (NNODE + 1);
  const int* esrc = esrc5 + (size_t)g * EDGES;
  int r0 = rowptr[node], r1 = rowptr[node + 1];
  if (r0 == r1) {
    out[(size_t)idx * DIM + tid] = 0.f;
    if (CLF && tid == 0) argm[node] = 0x7fffffff;
    return;
  }
  const float* dsrcg = dsrc + (size_t)g * NNODE * NH;
  float dd = ddst[(size_t)idx * NH + hh];
  float m = -__int_as_float(0x7f800000);
  for (int p = r0 + lane; p < r1; p += 32) {
    int s = esrc[p];
    float v = dsrcg[s * NH + hh] + dd;
    v = v > 0.f ? v : 0.2f * v;
    m = fmaxf(m, v);
  }
#pragma unroll
  for (int o = 16; o; o >>= 1) m = fmaxf(m, __shfl_xor_sync(0xffffffffu, m, o));

  const float* hbg = hbuf + (size_t)g * NNODE * DIM;
  float acc = 0.f, ssum = 0.f;
  for (int pb = r0; pb < r1; pb += 32) {
    int p = pb + lane;
    float ex = 0.f;
    int s = 0;
    if (p < r1) {
      s = esrc[p];
      float v = dsrcg[s * NH + hh] + dd;
      v = v > 0.f ? v : 0.2f * v;
      ex = expf(v - m);
    }
    int cnt = min(32, r1 - pb);
    for (int j = 0; j < cnt; j++) {
      float exj = __shfl_sync(0xffffffffu, ex, j);
      int sj = __shfl_sync(0xffffffffu, s, j);
      acc += exj * hbg[(size_t)sj * DIM + hh * HD + lane];
      ssum += exj;
    }
  }
  out[(size_t)idx * DIM + hh * HD + lane] = acc / (ssum + 1e-16f);

  if (CLF) {
    if (lane == 0) {
      sm[hh] = m;
      ss[hh] = ssum;
    }
    __syncthreads();
    float lmax = -__int_as_float(0x7f800000);
    for (int p = r0 + tid; p < r1; p += 256) {
      int s = esrc[p];
      float att = 0.f;
#pragma unroll
      for (int h2 = 0; h2 < NH; h2++) {
        float v = dsrcg[s * NH + h2] + ddst[(size_t)idx * NH + h2];
        v = v > 0.f ? v : 0.2f * v;
        att += expf(v - sm[h2]) / (ss[h2] + 1e-16f);
      }
      atts[p] = att;
      lmax = fmaxf(lmax, att);
    }
    redf[tid] = lmax;
    __syncthreads();
    for (int o = 128; o; o >>= 1) {
      if (tid < o) redf[tid] = fmaxf(redf[tid], redf[tid + o]);
      __syncthreads();
    }
    float bmax = redf[0];
    int lmin = 0x7fffffff;
    for (int p = r0 + tid; p < r1; p += 256)
      if (atts[p] == bmax) lmin = min(lmin, eid5[p]);
    redi[tid] = lmin;
    __syncthreads();
    for (int o = 128; o; o >>= 1) {
      if (tid < o) redi[tid] = min(redi[tid], redi[tid + o]);
      __syncthreads();
    }
    if (tid == 0) argm[node] = redi[0];
  }
}

// ------------------------------------------------------------------
// LSTM prep / step / pooling
// ------------------------------------------------------------------
__global__ void k_gather5(const float* __restrict__ aggB, const int* __restrict__ nbrs,
                          float* __restrict__ x, int* __restrict__ flag) {
  __shared__ int s;
  int n = blockIdx.x, g = blockIdx.y, d = threadIdx.x;
  int t = TT - 1 - g;
  if (d == 0) s = 0;
  __syncthreads();
  float v = aggB[((size_t)g * NNODE + nbrs[n]) * DIM + d];
  x[(size_t)n * TT * DIM + t * DIM + d] = v;
  if (v != 0.f) s = 1;
  __syncthreads();
  if (d == 0) flag[n * TT + t] = s;
}

__global__ void k_lens(const int* __restrict__ flag, int* lens, int* maxlen) {
  int n = blockIdx.x * 256 + threadIdx.x;
  if (n >= BNB) return;
  int c = 0;
#pragma unroll
  for (int t = 0; t < TT; t++) c += flag[n * TT + t];
  lens[n] = c;
  atomicMax(maxlen, c);
}

__global__ void k_buildrev(const float* __restrict__ x, const int* __restrict__ lens,
                           float* __restrict__ xrev) {
  int i = blockIdx.x * 256 + threadIdx.x;
  if (i >= BNB * TT * DIM) return;
  int d = i & (DIM - 1);
  int nt = i / DIM;
  int t = nt % TT, n = nt / TT;
  int idx = lens[n] - 1 - t;
  idx = max(0, min(idx, TT - 1));
  xrev[i] = x[(size_t)n * TT * DIM + idx * DIM + d];
}

// batched fwd+bwd: rr in [0, 2*BNB)
__global__ void k_lstmstep(const float* __restrict__ G, int t, float* __restrict__ h,
                           float* __restrict__ c, float* __restrict__ hs) {
  int rr = blockIdx.x, d = threadIdx.x;
  const float* g = G + (size_t)rr * (TT * GD) + t * GD;
  float gi = g[d], gf = g[DIM + d], gg = g[2 * DIM + d], go = g[3 * DIM + d];
  float cc = sigmf(gf) * c[rr * DIM + d] + sigmf(gi) * tanhf(gg);
  float hh = sigmf(go) * tanhf(cc);
  c[rr * DIM + d] = cc;
  h[rr * DIM + d] = hh;
  hs[(size_t)rr * TT * DIM + t * DIM + d] = hh;
}

__global__ void k_pool(const float* __restrict__ hs, const int* __restrict__ lens,
                       const int* __restrict__ maxlen, float* __restrict__ pooled) {
  int n = blockIdx.x, d = threadIdx.x;
  int ln = lens[n];
  float inv = 1.0f / (float)max(*maxlen, 1);
  const float* hsf = hs;
  const float* hsb = hs + (size_t)BNB * TT * DIM;
  float s = 0.f;
  for (int t = 0; t < ln; t++) {
    float f = hsf[(size_t)n * TT * DIM + t * DIM + d];
    float bb = hsb[(size_t)n * TT * DIM + (ln - 1 - t) * DIM + d];
    s += 0.5f * (f + bb);
  }
  pooled[n * DIM + d] = s * inv;
}

// ------------------------------------------------------------------
// clf helpers + head
// ------------------------------------------------------------------
__global__ void k_fillbias(const float* __restrict__ b, float* __restrict__ hbuf) {
  int n = blockIdx.x, d = threadIdx.x;
  hbuf[(size_t)n * DIM + d] = b[d];
}

__global__ void k_scatrows(const float* __restrict__ src, const int* __restrict__ idx,
                           float* __restrict__ dst) {
  int n = blockIdx.x, d = threadIdx.x;
  dst[(size_t)idx[n] * DIM + d] = src[(size_t)n * DIM + d];
}

__global__ void k_gatherrows(const float* __restrict__ src, const int* __restrict__ idx,
                             float* __restrict__ dst) {
  int n = blockIdx.x, d = threadIdx.x;
  dst[(size_t)n * DIM + d] = src[(size_t)idx[n] * DIM + d];
}

__global__ void k_mlp(const float* __restrict__ hclf, const float* __restrict__ scl,
                      const float* __restrict__ sft, const float* __restrict__ W1,
                      const float* __restrict__ b1, const float* __restrict__ W2,
                      const float* __restrict__ b2, const float* __restrict__ W3,
                      const float* __restrict__ b3, float* __restrict__ out, int out_size) {
  __shared__ float hrow[256], p1[32], p2[16];
  int i = blockIdx.x, tid = threadIdx.x;
  for (int k = tid; k < 256; k += 64) hrow[k] = hclf[(size_t)i * DIM + k] * scl[k] + sft[k];
  __syncthreads();
  if (tid < 32) {
    float s = b1[tid];
    for (int k = 0; k < 256; k++) s += hrow[k] * W1[k * 32 + tid];
    p1[tid] = tanhf(s);
  }
  __syncthreads();
  if (tid < 16) {
    float s = b2[tid];
    for (int k = 0; k < 32; k++) s += p1[k] * W2[k * 16 + tid];
    p2[tid] = tanhf(s);
  }
  __syncthreads();
  if (tid == 0) {
    float s = b3[0];
    for (int k = 0; k < 16; k++) s += p2[k] * W3[k];
    if (i < out_size) out[i] = 1.f / (1.f + expf(-s));
  }
}

__global__ void k_srcsel(const int* __restrict__ argm, const int* __restrict__ clf_nodes,
                         const int* __restrict__ src4, float* __restrict__ out, int out_size) {
  int i = blockIdx.x * 256 + threadIdx.x;
  if (i >= BCB) return;
  int a = argm[clf_nodes[i]];
  a = max(0, min(a, EDGES - 1));
  if (BCB + i < out_size) out[BCB + i] = (float)src4[a];
}

// ------------------------------------------------------------------
// host orchestration (side-stream overlap of prep work)
// ------------------------------------------------------------------
extern "C" void kernel_launch(void* const* d_in, const int* in_sizes, int n_in, void* d_out,
                              int out_size) {
  static Scratch* sp = nullptr;
  static cudaStream_t side = nullptr;
  static cudaEvent_t evFork = nullptr, evJoin = nullptr;
  if (!sp) {
    void* p = nullptr;
    cudaGetSymbolAddress(&p, S);
    sp = (Scratch*)p;
    cudaStreamCreateWithFlags(&side, cudaStreamNonBlocking);
    cudaEventCreateWithFlags(&evFork, cudaEventDisableTiming);
    cudaEventCreateWithFlags(&evJoin, cudaEventDisableTiming);
  }
  const float* emb = (const float*)d_in[0];
  const int* edges = (const int*)d_in[1];
  const int* clf_neighbors = (const int*)d_in[4];
  const int* clf_nodes = (const int*)d_in[5];
  const float* bn1_g = (const float*)d_in[6];
  const float* bn1_b = (const float*)d_in[7];
  const float* gnn_W = (const float*)d_in[8];
  const float* gnn_b = (const float*)d_in[9];
  const float* gnn_asrc = (const float*)d_in[10];
  const float* gnn_adst = (const float*)d_in[11];
  const float* lstm_Wih = (const float*)d_in[12];
  const float* lstm_Whh = (const float*)d_in[13];
  const float* lstm_bih = (const float*)d_in[14];
  const float* lstm_bhh = (const float*)d_in[15];
  const float* bn2_g = (const float*)d_in[16];
  const float* bn2_b = (const float*)d_in[17];
  const float* clf_W = (const float*)d_in[18];
  const float* clf_b = (const float*)d_in[19];
  const float* clf_asrc = (const float*)d_in[20];
  const float* clf_adst = (const float*)d_in[21];
  const float* W1 = (const float*)d_in[22];
  const float* b1 = (const float*)d_in[23];
  const float* W2 = (const float*)d_in[24];
  const float* b2 = (const float*)d_in[25];
  const float* W3 = (const float*)d_in[26];
  const float* b3 = (const float*)d_in[27];
  float* out = (float*)d_out;

  const int EB5 = (TT * EDGES + 255) / 256;
  const float MinvN = 1.0f / NNODE;
  const dim3 gBig(2, (TT * NNODE + 127) / 128);
  float* xrev = sp->xx + (size_t)BNB * TT * DIM;

  // main: W0 split + BN stats feed the big GEMM
  k_splitFT<<<128, 256>>>(gnn_W, sp->gWh, sp->gWl, DIM);
  k_zerof<<<8, 256>>>(sp->csum5, 2 * TT * DIM);

  // fork: independent prep (weight splits, bias, CSR build) on side stream
  cudaEventRecord(evFork, 0);
  cudaStreamWaitEvent(side, evFork, 0);
  k_splitFT<<<128, 256, 0, side>>>(gnn_W + DIM * DIM, sp->gWh + DIM * 128, sp->gWl + DIM * 128,
                                   DIM);
  k_splitFT<<<128, 256, 0, side>>>(clf_W, sp->cWh, sp->cWl, DIM);
  k_splitFD<<<1024, 256, 0, side>>>(lstm_Wih, sp->wihh, sp->wihl, 2 * GD);
  k_splitFD<<<1024, 256, 0, side>>>(lstm_Whh, sp->whhh, sp->whhl, 2 * GD);
  k_addb<<<(2 * GD + 255) / 256, 256, 0, side>>>(lstm_bih, lstm_bhh, sp->bias2, 2 * GD);
  k_zeroi<<<120, 256, 0, side>>>(sp->deg5, TT * NNODE);
  k_zeroi<<<120, 256, 0, side>>>(sp->fill5, TT * NNODE);
  k_count5<<<EB5, 256, 0, side>>>(edges, sp->deg5);
  k_scan5<<<TT, 1024, 0, side>>>(sp->deg5, sp->rowptr5);
  k_scatter5<<<EB5, 256, 0, side>>>(edges, sp->rowptr5, sp->fill5, sp->esrc5, sp->eid5);
  cudaEventRecord(evJoin, side);

  // main: BN stats + big layer-0 GEMM overlap the side chain
  k_bnstats5<<<dim3(8, TT, 25), 256>>>(emb, NNODE, sp->csum5, sp->csq5);
  k_mgemm<1><<<gBig, 256>>>(emb, DIM, sp->gWh, sp->gWl, nullptr, nullptr, sp->hbuf, DIM, gnn_b,
                            gnn_b, 1 << 30, sp->csum5, sp->csq5, bn1_g, bn1_b, MinvN, NNODE,
                            gnn_asrc, gnn_adst, sp->dsrc, sp->ddst, TT * NNODE);

  // join: aggregate needs the CSR (and later consumers need the splits)
  cudaStreamWaitEvent(0, evJoin, 0);
  k_aggregate<false><<<TT * NNODE, 256>>>(sp->rowptr5, sp->esrc5, sp->eid5, sp->hbuf, sp->dsrc,
                                          sp->ddst, sp->aggA, nullptr, nullptr);

  // layer 1
  k_zerof<<<8, 256>>>(sp->csum5, 2 * TT * DIM);
  k_bnstats5<<<dim3(8, TT, 25), 256>>>(sp->aggA, NNODE, sp->csum5, sp->csq5);
  k_mgemm<1><<<gBig, 256>>>(sp->aggA, DIM, sp->gWh + DIM * 128, sp->gWl + DIM * 128, nullptr,
                            nullptr, sp->hbuf, DIM, gnn_b + DIM, gnn_b + DIM, 1 << 30, sp->csum5,
                            sp->csq5, bn1_g, bn1_b, MinvN, NNODE, gnn_asrc + NH * HD,
                            gnn_adst + NH * HD, sp->dsrc, sp->ddst, TT * NNODE);
  k_aggregate<false><<<TT * NNODE, 256>>>(sp->rowptr5, sp->esrc5, sp->eid5, sp->hbuf, sp->dsrc,
                                          sp->ddst, sp->aggB, nullptr, nullptr);

  // sequences (graph g -> time step TT-1-g)
  k_gather5<<<dim3(BNB, TT), 256>>>(sp->aggB, clf_neighbors, sp->xx, sp->flag);
  k_zeroi<<<1, 32>>>(&sp->maxlen, 1);
  k_lens<<<(BNB + 255) / 256, 256>>>(sp->flag, sp->lens, &sp->maxlen);
  k_buildrev<<<(BNB * TT * DIM + 255) / 256, 256>>>(sp->xx, sp->lens, xrev);

  // batched bi-LSTM: input GEMM (fwd rows < 20480, bwd rows >= 20480)
  k_mgemm<0><<<dim3(8, (2 * BNB * TT) / 128), 256>>>(
      sp->xx, DIM, sp->wihh, sp->wihl, sp->wihh + GD * 128, sp->wihl + GD * 128, sp->Gpre, GD,
      sp->bias2, sp->bias2 + GD, BNB * TT, nullptr, nullptr, nullptr, nullptr, 0.f, 0, nullptr,
      nullptr, nullptr, nullptr, 2 * BNB * TT);
  k_zerof<<<(4 * BNB * DIM + 255) / 256, 256>>>(sp->h, 4 * BNB * DIM);  // h and c adjacent
  for (int t = 0; t < TT; t++) {
    k_mgemm<2><<<dim3(8, (2 * BNB) / 128), 256>>>(
        sp->h, DIM, sp->whhh, sp->whhl, sp->whhh + GD * 128, sp->whhl + GD * 128,
        sp->Gpre + t * GD, TT * GD, nullptr, nullptr, BNB, nullptr, nullptr, nullptr, nullptr,
        0.f, 0, nullptr, nullptr, nullptr, nullptr, 2 * BNB);
    k_lstmstep<<<2 * BNB, 256>>>(sp->Gpre, t, sp->h, sp->c, sp->hs);
  }
  k_pool<<<BNB, 256>>>(sp->hs, sp->lens, &sp->maxlen, sp->pooled);

  // clf conv (CSR of graph 4 reused)
  const int* src4 = edges + (size_t)(TT - 1) * 2 * EDGES;
  k_fillbias<<<NNODE, 256>>>(clf_b, sp->clfH);
  k_mgemm<0><<<dim3(2, BNB / 128), 256>>>(
      sp->pooled, DIM, sp->cWh, sp->cWl, nullptr, nullptr, sp->xx, DIM, clf_b, clf_b, 1 << 30,
      nullptr, nullptr, nullptr, nullptr, 0.f, 0, nullptr, nullptr, nullptr, nullptr, BNB);
  k_scatrows<<<BNB, 256>>>(sp->xx, clf_neighbors, sp->clfH);
  k_dots<<<NNODE, 256>>>(sp->clfH, clf_asrc, clf_adst, sp->dsrcC, sp->ddstC);
  k_aggregate<true><<<NNODE, 256>>>(sp->rowptr5 + 4 * (NNODE + 1), sp->esrc5 + 4 * EDGES,
                                    sp->eid5 + 4 * EDGES, sp->clfH, sp->dsrcC, sp->ddstC,
                                    sp->aggA, sp->atts, sp->argm);

  // head
  k_gatherrows<<<BCB, 256>>>(sp->aggA, clf_nodes, sp->hclf);
  k_zerof<<<8, 256>>>(sp->csum5, 2 * TT * DIM);
  k_bnstats5<<<dim3(8, 1, 4), 256>>>(sp->hclf, BCB, sp->csum5, sp->csq5);
  k_bnfin5<<<1, 256>>>(sp->csum5, sp->csq5, bn2_g, bn2_b, 1.0f / BCB, sp->scl5, sp->sft5);
  k_mlp<<<BCB, 64>>>(sp->hclf, sp->scl5, sp->sft5, W1, b1, W2, b2, W3, b3, out, out_size);
  k_srcsel<<<(BCB + 255) / 256, 256>>>(sp->argm, clf_nodes, src4, out, out_size);
}